// round 14
// baseline (speedup 1.0000x reference)
#include <cuda_runtime.h>
#include <cuda_bf16.h>
#include <math.h>

// Problem constants
#define PB 32
#define PN 4096
#define PD 768
#define PC 10
#define PK 16
#define NPROD (PB * PN / 8)      // 16384 producer CTAs (8 rows each)

// Scratch
__device__ unsigned g_scores_u[PB * PN];   // pre-flipped monotone scores
__device__ unsigned g_cnt[PB];             // per-batch producer arrival count (reset by consumer)

// Monotone 32-bit mapping: flip(a) > flip(b)  <=>  a > b (as floats)
__device__ __forceinline__ unsigned flip_f32(float s) {
    unsigned u = __float_as_uint(s);
    return (u & 0x80000000u) ? ~u : (u | 0x80000000u);
}

// ---------------------------------------------------------------------------
// Fused kernel. bid 0..31: consumer CTAs (scheduled FIRST, so they overlap
// the producer stream). bid 32..: producer CTAs, 8 rows each, HBM-roofline.
// Static smem kept tiny (~1.3 KB) so producer occupancy is unharmed.
// ---------------------------------------------------------------------------
__global__ void __launch_bounds__(256) fused_mil_kernel(
    const float* __restrict__ H,
    const float* __restrict__ w_score,
    const float* __restrict__ b_score,
    const float* __restrict__ W_cls,    // [D, C] row-major
    const float* __restrict__ b_cls,    // [C]
    float* __restrict__ logits_out,     // d_out, size PB*PC
    float* __restrict__ A_out)          // d_out + PB*PC, size PB*PN
{
    const int bid  = blockIdx.x;
    const int tid  = threadIdx.x;
    const int warp = tid >> 5;
    const int lane = tid & 31;
    const unsigned FULL = 0xFFFFFFFFu;
    const unsigned BIGI = 0xFFFFFFFFu;

    __shared__ unsigned cand_v[8 * PK];     // 512 B
    __shared__ unsigned cand_i[8 * PK];     // 512 B
    __shared__ int top[PK];                 // 64 B
    __shared__ float partial[8][PC];        // 320 B

    if (bid >= PB) {
        // ================= PRODUCER: 8 rows, one warp each =================
        const int pbid = bid - PB;
        if (tid < 8) A_out[pbid * 8 + tid] = 0.0f;   // zero own A entries

        const int row = pbid * 8 + warp;
        const float4* __restrict__ h4 = (const float4*)(H + (size_t)row * PD);
        const float4* __restrict__ w4 = (const float4*)w_score;

        float sum = 0.0f;
        #pragma unroll
        for (int k = 0; k < PD / 128; k++) {          // 6 float4 per lane
            float4 a = __ldcs(&h4[lane + k * 32]);    // streaming: evict-first
            float4 b = __ldg(&w4[lane + k * 32]);
            sum += a.x * b.x + a.y * b.y + a.z * b.z + a.w * b.w;
        }
        #pragma unroll
        for (int o = 16; o > 0; o >>= 1)
            sum += __shfl_down_sync(FULL, sum, o);

        if (lane == 0) g_scores_u[row] = flip_f32(sum + b_score[0]);

        __threadfence();                               // publish scores + A zeros
        __syncthreads();
        if (tid == 0) atomicAdd(&g_cnt[pbid >> 9], 1u);  // 512 CTAs per batch
        return;
    }

    // ==================== CONSUMER: one CTA per batch ====================
    const int b = bid;

    // Wait for this batch's 512 producer CTAs.
    if (tid == 0) {
        while (atomicAdd(&g_cnt[b], 0u) < 512u) __nanosleep(256);
    }
    __syncthreads();
    __threadfence();   // acquire ordering before reading scores

    // ---- Phase 1: per-warp top-16 over 512 scores (16 u32 regs/lane) ----
    {
        unsigned kv[16];
        const unsigned* __restrict__ sb = g_scores_u + b * PN + warp * 512;
        #pragma unroll
        for (int j = 0; j < 16; j++)
            kv[j] = sb[j * 32 + lane];                 // coalesced, L2-fresh
        const unsigned base = (unsigned)(warp * 512 + lane);

        #pragma unroll
        for (int it = 0; it < PK; it++) {
            unsigned bv = kv[0]; unsigned bj = 0;
            #pragma unroll
            for (int j = 1; j < 16; j++)
                if (kv[j] > bv) { bv = kv[j]; bj = (unsigned)j; }
            unsigned mx = __reduce_max_sync(FULL, bv);
            unsigned my = (bv == mx) ? (base + bj * 32) : BIGI;
            unsigned wi = __reduce_min_sync(FULL, my);
            unsigned r  = wi - base;                   // == j*32 iff my slot won
            #pragma unroll
            for (int j = 0; j < 16; j++)
                if (r == (unsigned)(j * 32)) kv[j] = 0u;
            if (lane == 0) { cand_v[warp * PK + it] = mx; cand_i[warp * PK + it] = wi; }
        }
    }
    __syncthreads();

    // ---- Phase 2: warp 0 merges 128 candidates -> global top-16 ----
    if (warp == 0) {
        unsigned vv[4], vi[4];
        #pragma unroll
        for (int j = 0; j < 4; j++) {
            vv[j] = cand_v[j * 32 + lane];
            vi[j] = cand_i[j * 32 + lane];
        }
        #pragma unroll
        for (int it = 0; it < PK; it++) {
            unsigned bv = vv[0], bi = vi[0];
            #pragma unroll
            for (int j = 1; j < 4; j++) {
                bool better = (vv[j] > bv) || (vv[j] == bv && vi[j] < bi);
                if (better) { bv = vv[j]; bi = vi[j]; }
            }
            unsigned mx = __reduce_max_sync(FULL, bv);
            unsigned my = (bv == mx) ? bi : BIGI;
            unsigned wi = __reduce_min_sync(FULL, my);
            #pragma unroll
            for (int j = 0; j < 4; j++)
                if (vv[j] == mx && vi[j] == wi) { vv[j] = 0u; vi[j] = BIGI; }
            if (lane == 0) top[it] = (int)wi;
        }
    }
    __syncthreads();

    // ---- Scatter attention mask A (zeros already published by producers) ----
    if (tid < PK) A_out[b * PN + top[tid]] = 1.0f / (float)PK;

    // ---- Gather + mean (all 8 warps, 24 lanes x float4) + partial GEMV ----
    const float4* __restrict__ H4 = (const float4*)H;
    float4 m = make_float4(0.f, 0.f, 0.f, 0.f);
    const int d4 = warp * 24 + ((lane < 24) ? lane : 23);   // clamped, in-bounds
    if (lane < 24) {
        #pragma unroll
        for (int j = 0; j < PK; j++) {
            float4 h = __ldcs(&H4[((size_t)b * PN + top[j]) * (PD / 4) + d4]);
            m.x += h.x; m.y += h.y; m.z += h.z; m.w += h.w;
        }
        const float inv = 1.0f / (float)PK;
        m.x *= inv; m.y *= inv; m.z *= inv; m.w *= inv;
    }
    // Weights for this lane's 4 rows: 40 CONTIGUOUS floats at W_cls + d4*40.
    float wr[4][PC];
    {
        const float4* __restrict__ Wg = (const float4*)(W_cls + d4 * 4 * PC);
        #pragma unroll
        for (int q = 0; q < 10; q++) {
            float4 w = __ldg(&Wg[q]);
            ((float*)wr)[q * 4 + 0] = w.x;
            ((float*)wr)[q * 4 + 1] = w.y;
            ((float*)wr)[q * 4 + 2] = w.z;
            ((float*)wr)[q * 4 + 3] = w.w;
        }
    }
    float p[PC];
    #pragma unroll
    for (int c = 0; c < PC; c++)
        p[c] = m.x * wr[0][c] + m.y * wr[1][c] + m.z * wr[2][c] + m.w * wr[3][c];
    #pragma unroll
    for (int c = 0; c < PC; c++) {
        #pragma unroll
        for (int o = 16; o > 0; o >>= 1)
            p[c] += __shfl_xor_sync(FULL, p[c], o);
    }
    if (lane == 0) {
        #pragma unroll
        for (int c = 0; c < PC; c++) partial[warp][c] = p[c];
    }
    __syncthreads();

    // ---- Final logits ----
    if (tid < PC) {
        float acc = b_cls[tid];
        #pragma unroll
        for (int w = 0; w < 8; w++) acc += partial[w][tid];
        logits_out[b * PC + tid] = acc;
    }

    // ---- Reset this batch's counter for the next graph replay ----
    __syncthreads();
    if (tid == 0) atomicExch(&g_cnt[b], 0u);
}

// ---------------------------------------------------------------------------
// Launch: single fused kernel; consumers are bid 0..31 (scheduled first).
// Inputs (metadata order): H [B,N,D] f32, w_score [D] f32, b_score [] f32,
//                          W_cls [D,C] f32, b_cls [C] f32.
// Output: logits [B,C] (320 floats) followed by A [B,N,1] (131072 floats).
// ---------------------------------------------------------------------------
extern "C" void kernel_launch(void* const* d_in, const int* in_sizes, int n_in,
                              void* d_out, int out_size)
{
    const float* H       = (const float*)d_in[0];
    const float* w_score = (const float*)d_in[1];
    const float* b_score = (const float*)d_in[2];
    const float* W_cls   = (const float*)d_in[3];
    const float* b_cls   = (const float*)d_in[4];

    float* logits_out = (float*)d_out;
    float* A_out      = (float*)d_out + PB * PC;

    fused_mil_kernel<<<NPROD + PB, 256>>>(H, w_score, b_score,
                                          W_cls, b_cls, logits_out, A_out);
}

// round 15
// speedup vs baseline: 1.2857x; 1.2857x over previous
#include <cuda_runtime.h>
#include <cuda_bf16.h>
#include <math.h>

// Problem constants
#define PB 32
#define PN 4096
#define PD 768
#define PC 10
#define PK 16
#define NBIN 2048          // 11-bit key-prefix histogram
#define CAP 512            // candidate buffer capacity

// Scratch: per-(b,n) pre-flipped scores (monotone u32). 512 KB.
__device__ unsigned g_scores_u[PB * PN];

// Monotone 32-bit mapping: flip(a) > flip(b)  <=>  a > b (as floats)
__device__ __forceinline__ unsigned flip_f32(float s) {
    unsigned u = __float_as_uint(s);
    return (u & 0x80000000u) ? ~u : (u | 0x80000000u);
}

// ---------------------------------------------------------------------------
// Kernel 1: scores s[b,n] = dot(H[b,n,:], w) + b_score. One warp per row.
// H streamed with __ldcs; ~6.9 TB/s measured across 6 rounds — frozen.
// Also zeroes the A output region.
// ---------------------------------------------------------------------------
__global__ void __launch_bounds__(256) score_kernel(
    const float* __restrict__ H,
    const float* __restrict__ w_score,
    const float* __restrict__ b_score,
    float* __restrict__ A_out)
{
    const int tid_global = blockIdx.x * blockDim.x + threadIdx.x;
    const int warp = tid_global >> 5;
    const int lane = threadIdx.x & 31;

    if (tid_global < PB * PN) A_out[tid_global] = 0.0f;
    if (warp >= PB * PN) return;

    const float4* __restrict__ h4 = (const float4*)(H + (size_t)warp * PD);
    const float4* __restrict__ w4 = (const float4*)w_score;

    float sum = 0.0f;
    #pragma unroll
    for (int k = 0; k < PD / 128; k++) {
        float4 a = __ldcs(&h4[lane + k * 32]);
        float4 b = __ldg(&w4[lane + k * 32]);
        sum += a.x * b.x + a.y * b.y + a.z * b.z + a.w * b.w;
    }
    #pragma unroll
    for (int o = 16; o > 0; o >>= 1)
        sum += __shfl_down_sync(0xFFFFFFFFu, sum, o);

    if (lane == 0) g_scores_u[warp] = flip_f32(sum + b_score[0]);
}

// ---------------------------------------------------------------------------
// Kernel 2: histogram-threshold top-16 + A scatter + gather/mean + classifier.
// 1 CTA per batch, 256 threads. (R10 structure; GEMV now register-direct.)
// ---------------------------------------------------------------------------
__global__ void __launch_bounds__(256) topk_epilogue_kernel(
    const float* __restrict__ H,
    const float* __restrict__ W_cls,   // [D, C] row-major
    const float* __restrict__ b_cls,   // [C]
    float* __restrict__ logits_out,    // d_out, size PB*PC
    float* __restrict__ A_out)         // d_out + PB*PC, size PB*PN
{
    const int b    = blockIdx.x;
    const int tid  = threadIdx.x;
    const int warp = tid >> 5;
    const int lane = tid & 31;
    const unsigned FULL = 0xFFFFFFFFu;

    __shared__ unsigned hist[NBIN];                   // 8192 B
    __shared__ unsigned part[256];                    // 1024 B
    __shared__ unsigned long long candbuf[CAP];       // 4096 B
    __shared__ unsigned sT, ccnt;
    __shared__ int topS[PK];
    __shared__ float partial[8][PC];

    #pragma unroll
    for (int i = 0; i < NBIN / 256; i++) hist[tid + i * 256] = 0u;
    if (tid == 0) ccnt = 0u;
    __syncthreads();

    // ---- 1. Load 16 keys/thread + conflict-aggregated histogram ----
    unsigned kv[16];
    const unsigned* __restrict__ sb = g_scores_u + b * PN;
    #pragma unroll
    for (int j = 0; j < 16; j++) kv[j] = sb[j * 256 + tid];   // coalesced
    #pragma unroll
    for (int j = 0; j < 16; j++) {
        unsigned bin = kv[j] >> 21;
        unsigned mk  = __match_any_sync(FULL, bin);
        if (lane == __ffs(mk) - 1) atomicAdd(&hist[bin], (unsigned)__popc(mk));
    }
    __syncthreads();

    // ---- 2. Per-thread partial bin sums ----
    {
        unsigned s = 0;
        #pragma unroll
        for (int i = 0; i < NBIN / 256; i++) s += hist[tid * (NBIN / 256) + i];
        part[tid] = s;
    }
    __syncthreads();

    // ---- 3. Warp 0: find threshold bin T (largest bin with suffix >= 16) ----
    if (warp == 0) {
        unsigned pa = 0;                                // lane covers bins [lane*64,(lane+1)*64)
        #pragma unroll
        for (int i = 0; i < 8; i++) pa += part[lane * 8 + i];
        unsigned sfx = pa;
        #pragma unroll
        for (int o = 1; o < 32; o <<= 1) {
            unsigned u = __shfl_down_sync(FULL, sfx, o);
            if (lane + o < 32) sfx += u;
        }
        unsigned ball = __ballot_sync(FULL, sfx >= PK);
        int l1 = 31 - __clz(ball);                      // window lane
        unsigned sfx_next = __shfl_down_sync(FULL, sfx, 1);
        if (lane == 31) sfx_next = 0u;
        unsigned C_above = __shfl_sync(FULL, sfx_next, l1);  // keys in bins >= (l1+1)*64

        int base = l1 * 64;
        unsigned h0 = hist[base + 2 * lane];
        unsigned h1 = hist[base + 2 * lane + 1];
        unsigned tb = h0 + h1;
        unsigned sfx2 = tb;
        #pragma unroll
        for (int o = 1; o < 32; o <<= 1) {
            unsigned u = __shfl_down_sync(FULL, sfx2, o);
            if (lane + o < 32) sfx2 += u;
        }
        unsigned nxt = __shfl_down_sync(FULL, sfx2, 1);
        if (lane == 31) nxt = 0u;
        unsigned s1 = C_above + nxt + h1;               // suffix at bin base+2l+1
        unsigned s0 = s1 + h0;                          // suffix at bin base+2l
        int p = (s1 >= PK) ? (2 * lane + 1) : ((s0 >= PK) ? (2 * lane) : -1);
        int Toff = __reduce_max_sync(FULL, p);
        if (lane == 0) sT = (unsigned)(base + Toff);
    }
    __syncthreads();

    // ---- 4. Collect candidates with bin >= T ----
    {
        unsigned T = sT;
        #pragma unroll
        for (int j = 0; j < 16; j++) {
            if ((kv[j] >> 21) >= T) {
                unsigned pos = atomicAdd(&ccnt, 1u);
                if (pos < CAP) {
                    unsigned gidx = (unsigned)(j * 256 + tid);
                    candbuf[pos] = ((unsigned long long)kv[j] << 32) | (0xFFFFFFFFu - gidx);
                }
            }
        }
    }
    __syncthreads();

    // ---- 5. Exact top-16 of candidates ----
    int cc = (int)ccnt; if (cc > CAP) cc = CAP;
    int t[PK]; unsigned myTop = 0;
    if (cc <= 64) {
        // Bitonic sort 64 (ascending of ~packed == descending of packed),
        // run redundantly by all warps. pos p0 = lane, p1 = lane + 32.
        unsigned long long w0 = (lane      < cc) ? ~candbuf[lane]      : ~0ull;
        unsigned long long w1 = (lane + 32 < cc) ? ~candbuf[lane + 32] : ~0ull;
        #pragma unroll
        for (int k = 2; k <= 64; k <<= 1) {
            #pragma unroll
            for (int j = k >> 1; j > 0; j >>= 1) {
                if (j == 32) {                          // only at k==64; ascending
                    unsigned long long mn = (w0 < w1) ? w0 : w1;
                    unsigned long long mx = (w0 < w1) ? w1 : w0;
                    w0 = mn; w1 = mx;
                } else {
                    {
                        unsigned long long y = __shfl_xor_sync(FULL, w0, j);
                        int p = lane;
                        bool keepmin = (((p & k) == 0) == ((p & j) == 0));
                        unsigned long long mn = (w0 < y) ? w0 : y;
                        unsigned long long mx = (w0 < y) ? y : w0;
                        w0 = keepmin ? mn : mx;
                    }
                    {
                        unsigned long long y = __shfl_xor_sync(FULL, w1, j);
                        int p = lane + 32;
                        bool keepmin = (((p & k) == 0) == ((p & j) == 0));
                        unsigned long long mn = (w1 < y) ? w1 : y;
                        unsigned long long mx = (w1 < y) ? y : w1;
                        w1 = keepmin ? mn : mx;
                    }
                }
            }
        }
        myTop = (unsigned)w0;                           // gidx for lanes 0..15
        #pragma unroll
        for (int j = 0; j < PK; j++) t[j] = (int)__shfl_sync(FULL, myTop, j);
    } else {
        // Rare fallback: iterative selection over <=CAP candidates (warp 0)
        if (warp == 0) {
            unsigned long long v[16];
            #pragma unroll
            for (int j = 0; j < 16; j++) {
                int i = lane + j * 32;
                v[j] = (i < cc) ? candbuf[i] : 0ull;
            }
            #pragma unroll
            for (int it = 0; it < PK; it++) {
                unsigned long long bk = v[0];
                #pragma unroll
                for (int j = 1; j < 16; j++) bk = (v[j] > bk) ? v[j] : bk;
                unsigned long long mx = bk;
                #pragma unroll
                for (int o = 16; o > 0; o >>= 1) {
                    unsigned long long q = __shfl_xor_sync(FULL, mx, o);
                    mx = (q > mx) ? q : mx;
                }
                #pragma unroll
                for (int j = 0; j < 16; j++) if (v[j] == mx) v[j] = 0ull;
                if (lane == 0) topS[it] = (int)(0xFFFFFFFFu - (unsigned)mx);
            }
        }
        __syncthreads();
        #pragma unroll
        for (int j = 0; j < PK; j++) t[j] = topS[j];
        myTop = (lane < PK) ? (unsigned)topS[lane] : 0u;
    }

    // ---- 6. Scatter attention mask A ----
    if (warp == 0 && lane < PK) A_out[b * PN + (int)myTop] = 1.0f / (float)PK;

    // ---- 7. Load this lane's 40 contiguous W floats (overlaps the gather) ----
    const int d4 = warp * 24 + ((lane < 24) ? lane : 23);   // clamped, in-bounds
    float wr[4][PC];
    {
        const float4* __restrict__ Wg = (const float4*)(W_cls + d4 * 4 * PC);
        #pragma unroll
        for (int q = 0; q < 10; q++) {
            float4 w = __ldg(&Wg[q]);
            ((float*)wr)[q * 4 + 0] = w.x;
            ((float*)wr)[q * 4 + 1] = w.y;
            ((float*)wr)[q * 4 + 2] = w.z;
            ((float*)wr)[q * 4 + 3] = w.w;
        }
    }

    // ---- 8. Gather + mean (all warps, 24 lanes x float4) + partial GEMV ----
    const float4* __restrict__ H4 = (const float4*)H;
    float4 m = make_float4(0.f, 0.f, 0.f, 0.f);
    if (lane < 24) {
        #pragma unroll
        for (int j = 0; j < PK; j++) {
            float4 h = __ldcs(&H4[((size_t)b * PN + t[j]) * (PD / 4) + d4]);
            m.x += h.x; m.y += h.y; m.z += h.z; m.w += h.w;
        }
        const float inv = 1.0f / (float)PK;
        m.x *= inv; m.y *= inv; m.z *= inv; m.w *= inv;
    }
    float p[PC];
    #pragma unroll
    for (int c = 0; c < PC; c++)
        p[c] = m.x * wr[0][c] + m.y * wr[1][c] + m.z * wr[2][c] + m.w * wr[3][c];
    #pragma unroll
    for (int c = 0; c < PC; c++) {
        #pragma unroll
        for (int o = 16; o > 0; o >>= 1)
            p[c] += __shfl_xor_sync(FULL, p[c], o);
    }
    if (lane == 0) {
        #pragma unroll
        for (int c = 0; c < PC; c++) partial[warp][c] = p[c];
    }
    __syncthreads();

    // ---- 9. Final logits ----
    if (tid < PC) {
        float acc = b_cls[tid];
        #pragma unroll
        for (int w = 0; w < 8; w++) acc += partial[w][tid];
        logits_out[b * PC + tid] = acc;
    }
}

// ---------------------------------------------------------------------------
// Launch
// Inputs (metadata order): H [B,N,D] f32, w_score [D] f32, b_score [] f32,
//                          W_cls [D,C] f32, b_cls [C] f32.
// Output: logits [B,C] (320 floats) followed by A [B,N,1] (131072 floats).
// ---------------------------------------------------------------------------
extern "C" void kernel_launch(void* const* d_in, const int* in_sizes, int n_in,
                              void* d_out, int out_size)
{
    const float* H       = (const float*)d_in[0];
    const float* w_score = (const float*)d_in[1];
    const float* b_score = (const float*)d_in[2];
    const float* W_cls   = (const float*)d_in[3];
    const float* b_cls   = (const float*)d_in[4];

    float* logits_out = (float*)d_out;
    float* A_out      = (float*)d_out + PB * PC;

    const int rows = PB * PN;
    const int blocks1 = (rows + 7) / 8;
    score_kernel<<<blocks1, 256>>>(H, w_score, b_score, A_out);

    topk_epilogue_kernel<<<PB, 256>>>(H, W_cls, b_cls, logits_out, A_out);
}

// round 16
// speedup vs baseline: 1.3229x; 1.0289x over previous
#include <cuda_runtime.h>
#include <cuda_bf16.h>
#include <cuda_pipeline.h>
#include <math.h>

// Problem constants
#define PB 32
#define PN 4096
#define PD 768
#define PC 10
#define PK 16
#define NBIN 2048          // 11-bit key-prefix histogram
#define CAP 512            // candidate buffer capacity

// Scratch: per-(b,n) pre-flipped scores (monotone u32). 512 KB.
__device__ unsigned g_scores_u[PB * PN];

// Monotone 32-bit mapping: flip(a) > flip(b)  <=>  a > b (as floats)
__device__ __forceinline__ unsigned flip_f32(float s) {
    unsigned u = __float_as_uint(s);
    return (u & 0x80000000u) ? ~u : (u | 0x80000000u);
}

// ---------------------------------------------------------------------------
// Kernel 1: scores s[b,n] = dot(H[b,n,:], w) + b_score. One warp per row.
// ~6.9 TB/s measured across 6 rounds — body frozen; adds only the PDL
// trigger at the very end (piggybacks on CTA exit, no stream-loop cost).
// Also zeroes the A output region.
// ---------------------------------------------------------------------------
__global__ void __launch_bounds__(256) score_kernel(
    const float* __restrict__ H,
    const float* __restrict__ w_score,
    const float* __restrict__ b_score,
    float* __restrict__ A_out)
{
    const int tid_global = blockIdx.x * blockDim.x + threadIdx.x;
    const int warp = tid_global >> 5;
    const int lane = threadIdx.x & 31;

    if (tid_global < PB * PN) A_out[tid_global] = 0.0f;

    if (warp < PB * PN) {
        const float4* __restrict__ h4 = (const float4*)(H + (size_t)warp * PD);
        const float4* __restrict__ w4 = (const float4*)w_score;

        float sum = 0.0f;
        #pragma unroll
        for (int k = 0; k < PD / 128; k++) {
            float4 a = __ldcs(&h4[lane + k * 32]);
            float4 b = __ldg(&w4[lane + k * 32]);
            sum += a.x * b.x + a.y * b.y + a.z * b.z + a.w * b.w;
        }
        #pragma unroll
        for (int o = 16; o > 0; o >>= 1)
            sum += __shfl_down_sync(0xFFFFFFFFu, sum, o);

        if (lane == 0) g_scores_u[warp] = flip_f32(sum + b_score[0]);
    }

#if __CUDA_ARCH__ >= 900
    cudaTriggerProgrammaticLaunchCompletion();
#endif
}

// ---------------------------------------------------------------------------
// Kernel 2: histogram-threshold top-16 + A scatter + gather/mean + classifier.
// 1 CTA per batch, 256 threads. PDL: prologue (hist zero + W cp.async) runs
// BEFORE cudaGridDependencySynchronize(), overlapped with k1's tail.
// ---------------------------------------------------------------------------
__global__ void __launch_bounds__(256) topk_epilogue_kernel(
    const float* __restrict__ H,
    const float* __restrict__ W_cls,   // [D, C] row-major
    const float* __restrict__ b_cls,   // [C]
    float* __restrict__ logits_out,    // d_out, size PB*PC
    float* __restrict__ A_out)         // d_out + PB*PC, size PB*PN
{
    const int b    = blockIdx.x;
    const int tid  = threadIdx.x;
    const int warp = tid >> 5;
    const int lane = tid & 31;
    const unsigned FULL = 0xFFFFFFFFu;

    __shared__ __align__(16) float sW[PD * PC];       // 30720 B
    __shared__ unsigned hist[NBIN];                   // 8192 B
    __shared__ unsigned part[256];                    // 1024 B
    __shared__ unsigned long long candbuf[CAP];       // 4096 B
    __shared__ unsigned sT, ccnt;
    __shared__ int topS[PK];
    __shared__ float partial[8][PC];

    // ---- 0. PDL prologue: W_cls -> smem + hist zero (overlaps k1 tail) ----
    {
        const float4* __restrict__ Wg = (const float4*)W_cls;
        float4* Ws = (float4*)sW;
        #pragma unroll
        for (int i = 0; i < 8; i++) {
            int idx = tid + i * 256;
            if (idx < (PD * PC) / 4)
                __pipeline_memcpy_async(&Ws[idx], &Wg[idx], 16);
        }
        __pipeline_commit();
    }
    #pragma unroll
    for (int i = 0; i < NBIN / 256; i++) hist[tid + i * 256] = 0u;
    if (tid == 0) ccnt = 0u;

#if __CUDA_ARCH__ >= 900
    cudaGridDependencySynchronize();   // wait for ALL of k1's CTAs' writes
#endif
    __syncthreads();

    // ---- 1. Load 16 keys/thread + conflict-aggregated histogram ----
    unsigned kv[16];
    const unsigned* __restrict__ sb = g_scores_u + b * PN;
    #pragma unroll
    for (int j = 0; j < 16; j++) kv[j] = sb[j * 256 + tid];   // coalesced
    #pragma unroll
    for (int j = 0; j < 16; j++) {
        unsigned bin = kv[j] >> 21;
        unsigned mk  = __match_any_sync(FULL, bin);
        if (lane == __ffs(mk) - 1) atomicAdd(&hist[bin], (unsigned)__popc(mk));
    }
    __syncthreads();

    // ---- 2. Per-thread partial bin sums ----
    {
        unsigned s = 0;
        #pragma unroll
        for (int i = 0; i < NBIN / 256; i++) s += hist[tid * (NBIN / 256) + i];
        part[tid] = s;
    }
    __syncthreads();

    // ---- 3. Warp 0: find threshold bin T (largest bin with suffix >= 16) ----
    if (warp == 0) {
        unsigned pa = 0;
        #pragma unroll
        for (int i = 0; i < 8; i++) pa += part[lane * 8 + i];
        unsigned sfx = pa;
        #pragma unroll
        for (int o = 1; o < 32; o <<= 1) {
            unsigned u = __shfl_down_sync(FULL, sfx, o);
            if (lane + o < 32) sfx += u;
        }
        unsigned ball = __ballot_sync(FULL, sfx >= PK);
        int l1 = 31 - __clz(ball);
        unsigned sfx_next = __shfl_down_sync(FULL, sfx, 1);
        if (lane == 31) sfx_next = 0u;
        unsigned C_above = __shfl_sync(FULL, sfx_next, l1);

        int base = l1 * 64;
        unsigned h0 = hist[base + 2 * lane];
        unsigned h1 = hist[base + 2 * lane + 1];
        unsigned tb = h0 + h1;
        unsigned sfx2 = tb;
        #pragma unroll
        for (int o = 1; o < 32; o <<= 1) {
            unsigned u = __shfl_down_sync(FULL, sfx2, o);
            if (lane + o < 32) sfx2 += u;
        }
        unsigned nxt = __shfl_down_sync(FULL, sfx2, 1);
        if (lane == 31) nxt = 0u;
        unsigned s1 = C_above + nxt + h1;
        unsigned s0 = s1 + h0;
        int p = (s1 >= PK) ? (2 * lane + 1) : ((s0 >= PK) ? (2 * lane) : -1);
        int Toff = __reduce_max_sync(FULL, p);
        if (lane == 0) sT = (unsigned)(base + Toff);
    }
    __syncthreads();

    // ---- 4. Collect candidates with bin >= T ----
    {
        unsigned T = sT;
        #pragma unroll
        for (int j = 0; j < 16; j++) {
            if ((kv[j] >> 21) >= T) {
                unsigned pos = atomicAdd(&ccnt, 1u);
                if (pos < CAP) {
                    unsigned gidx = (unsigned)(j * 256 + tid);
                    candbuf[pos] = ((unsigned long long)kv[j] << 32) | (0xFFFFFFFFu - gidx);
                }
            }
        }
    }
    __pipeline_wait_prior(0);
    __syncthreads();

    // ---- 5. Exact top-16 of candidates ----
    int cc = (int)ccnt; if (cc > CAP) cc = CAP;
    int t[PK]; unsigned myTop = 0;
    if (cc <= 64) {
        unsigned long long w0 = (lane      < cc) ? ~candbuf[lane]      : ~0ull;
        unsigned long long w1 = (lane + 32 < cc) ? ~candbuf[lane + 32] : ~0ull;
        #pragma unroll
        for (int k = 2; k <= 64; k <<= 1) {
            #pragma unroll
            for (int j = k >> 1; j > 0; j >>= 1) {
                if (j == 32) {
                    unsigned long long mn = (w0 < w1) ? w0 : w1;
                    unsigned long long mx = (w0 < w1) ? w1 : w0;
                    w0 = mn; w1 = mx;
                } else {
                    {
                        unsigned long long y = __shfl_xor_sync(FULL, w0, j);
                        int p = lane;
                        bool keepmin = (((p & k) == 0) == ((p & j) == 0));
                        unsigned long long mn = (w0 < y) ? w0 : y;
                        unsigned long long mx = (w0 < y) ? y : w0;
                        w0 = keepmin ? mn : mx;
                    }
                    {
                        unsigned long long y = __shfl_xor_sync(FULL, w1, j);
                        int p = lane + 32;
                        bool keepmin = (((p & k) == 0) == ((p & j) == 0));
                        unsigned long long mn = (w1 < y) ? w1 : y;
                        unsigned long long mx = (w1 < y) ? y : w1;
                        w1 = keepmin ? mn : mx;
                    }
                }
            }
        }
        myTop = (unsigned)w0;
        #pragma unroll
        for (int j = 0; j < PK; j++) t[j] = (int)__shfl_sync(FULL, myTop, j);
    } else {
        if (warp == 0) {
            unsigned long long v[16];
            #pragma unroll
            for (int j = 0; j < 16; j++) {
                int i = lane + j * 32;
                v[j] = (i < cc) ? candbuf[i] : 0ull;
            }
            #pragma unroll
            for (int it = 0; it < PK; it++) {
                unsigned long long bk = v[0];
                #pragma unroll
                for (int j = 1; j < 16; j++) bk = (v[j] > bk) ? v[j] : bk;
                unsigned long long mx = bk;
                #pragma unroll
                for (int o = 16; o > 0; o >>= 1) {
                    unsigned long long q = __shfl_xor_sync(FULL, mx, o);
                    mx = (q > mx) ? q : mx;
                }
                #pragma unroll
                for (int j = 0; j < 16; j++) if (v[j] == mx) v[j] = 0ull;
                if (lane == 0) topS[it] = (int)(0xFFFFFFFFu - (unsigned)mx);
            }
        }
        __syncthreads();
        #pragma unroll
        for (int j = 0; j < PK; j++) t[j] = topS[j];
        myTop = (lane < PK) ? (unsigned)topS[lane] : 0u;
    }

    // ---- 6. Scatter attention mask A ----
    if (warp == 0 && lane < PK) A_out[b * PN + (int)myTop] = 1.0f / (float)PK;

    // ---- 7. Gather + mean (all warps, 24 lanes x float4) + partial GEMV ----
    const float4* __restrict__ H4 = (const float4*)H;
    float4 m = make_float4(0.f, 0.f, 0.f, 0.f);
    const int d4 = warp * 24 + ((lane < 24) ? lane : 23);
    if (lane < 24) {
        #pragma unroll
        for (int j = 0; j < PK; j++) {
            float4 h = __ldcs(&H4[((size_t)b * PN + t[j]) * (PD / 4) + d4]);
            m.x += h.x; m.y += h.y; m.z += h.z; m.w += h.w;
        }
        const float inv = 1.0f / (float)PK;
        m.x *= inv; m.y *= inv; m.z *= inv; m.w *= inv;
    }
    float p[PC];
    #pragma unroll
    for (int c = 0; c < PC; c++) {
        const float* w0 = sW + (d4 * 4) * PC + c;
        p[c] = m.x * w0[0] + m.y * w0[PC] + m.z * w0[2 * PC] + m.w * w0[3 * PC];
    }
    #pragma unroll
    for (int c = 0; c < PC; c++) {
        #pragma unroll
        for (int o = 16; o > 0; o >>= 1)
            p[c] += __shfl_xor_sync(FULL, p[c], o);
    }
    if (lane == 0) {
        #pragma unroll
        for (int c = 0; c < PC; c++) partial[warp][c] = p[c];
    }
    __syncthreads();

    // ---- 8. Final logits ----
    if (tid < PC) {
        float acc = b_cls[tid];
        #pragma unroll
        for (int w = 0; w < 8; w++) acc += partial[w][tid];
        logits_out[b * PC + tid] = acc;
    }
}

// ---------------------------------------------------------------------------
// Launch: k1 normal; k2 via cudaLaunchKernelEx with PDL attribute so its
// prologue overlaps k1's tail. Falls back to a plain launch on error.
// ---------------------------------------------------------------------------
extern "C" void kernel_launch(void* const* d_in, const int* in_sizes, int n_in,
                              void* d_out, int out_size)
{
    const float* H       = (const float*)d_in[0];
    const float* w_score = (const float*)d_in[1];
    const float* b_score = (const float*)d_in[2];
    const float* W_cls   = (const float*)d_in[3];
    const float* b_cls   = (const float*)d_in[4];

    float* logits_out = (float*)d_out;
    float* A_out      = (float*)d_out + PB * PC;

    const int rows = PB * PN;
    const int blocks1 = (rows + 7) / 8;
    score_kernel<<<blocks1, 256>>>(H, w_score, b_score, A_out);

    cudaLaunchConfig_t cfg = {};
    cfg.gridDim  = dim3(PB, 1, 1);
    cfg.blockDim = dim3(256, 1, 1);
    cfg.dynamicSmemBytes = 0;
    cfg.stream = 0;                       // legacy default stream (captured)
    cudaLaunchAttribute attr[1];
    attr[0].id = cudaLaunchAttributeProgrammaticStreamSerialization;
    attr[0].val.programmaticStreamSerializationAllowed = 1;
    cfg.attrs = attr;
    cfg.numAttrs = 1;

    cudaError_t e = cudaLaunchKernelEx(&cfg, topk_epilogue_kernel,
                                       H, W_cls, b_cls, logits_out, A_out);
    if (e != cudaSuccess) {
        // PDL unsupported in this context: plain serialized launch.
        topk_epilogue_kernel<<<PB, 256>>>(H, W_cls, b_cls, logits_out, A_out);
    }
}